// round 16
// baseline (speedup 1.0000x reference)
#include <cuda_runtime.h>
#include <cuda_bf16.h>
#include <cuda_fp16.h>
#include <cstdint>
#include <cstddef>

// ---------------------------------------------------------------------------
// Problem constants (fixed by the dataset)
// ---------------------------------------------------------------------------
#define Q_   8192
#define C_   256
#define LVL  4
#define NH_  8
#define DH_  32
#define HMAX_ 128

#define ROWS_PER_B 21760   // 16384+4096+1024+256
#define NROWS      43520   // 2 * ROWS_PER_B

// ---------------------------------------------------------------------------
// Scratch (device globals; no allocation allowed)
// ---------------------------------------------------------------------------
__device__ __half g_vproj[(size_t)NROWS * C_];  // projected valid values (fp16)
__device__ float  g_offs [(size_t)Q_ * 256];    // sampling-offset raw proj
__device__ float  g_awr  [(size_t)Q_ * 128];    // attention-weight logits
__device__ __half g_agg  [(size_t)Q_ * C_];     // per-query aggregated heads (fp16)

// bf16x3 weight image (combined W_so|W_aw): per (kb32, nb64): [hi 5120B | lo 5120B]
__device__ __align__(16) char g_wqc_img[491520];   // 384 rows: 8 kb x 6 nb x 10240
// fp16 weight images: per (kb, nb64) blob: 5120B (fp16x2 pairs)
__device__ __align__(16) char g_wvh_img[163840];   // W_v: 8 kb x 4 nb x 5120
__device__ __align__(16) char g_woh_img[163840];   // W_o: 8 kb x 4 nb x 5120

// ---------------------------------------------------------------------------
// Row mapping: compact row r -> offset into values[B,128,128,L,C]
// ---------------------------------------------------------------------------
__device__ __forceinline__ size_t map_a_row(int r) {
    int b  = r / ROWS_PER_B;
    int rr = r - b * ROWS_PER_B;
    int l, base, W;
    if (rr < 16384)      { l = 0; base = 0;     W = 128; }
    else if (rr < 20480) { l = 1; base = 16384; W = 64;  }
    else if (rr < 21504) { l = 2; base = 20480; W = 32;  }
    else                 { l = 3; base = 21504; W = 16;  }
    int idx = rr - base;
    int y = idx / W;
    int x = idx - y * W;
    return ((((size_t)b * HMAX_ + y) * HMAX_ + x) * LVL + l) * C_;
}

// ---------------------------------------------------------------------------
// helpers
// ---------------------------------------------------------------------------
__device__ __forceinline__ uint32_t smem_u32(const void* p) {
    uint32_t a;
    asm("{ .reg .u64 t; cvta.to.shared.u64 t, %1; cvt.u32.u64 %0, t; }"
        : "=r"(a) : "l"(p));
    return a;
}

__device__ __forceinline__ uint32_t pack_bf16x2(float e0, float e1) {
    uint32_t r;
    asm("cvt.rn.bf16x2.f32 %0, %1, %2;" : "=r"(r) : "f"(e1), "f"(e0));
    return r;
}

__device__ __forceinline__ uint32_t pack_f16x2(float e0, float e1) {
    uint32_t r;
    asm("cvt.rn.f16x2.f32 %0, %1, %2;" : "=r"(r) : "f"(e1), "f"(e0));
    return r;
}

__device__ __forceinline__ float bf_hi(float x) {
    return __bfloat162float(__float2bfloat16_rn(x));
}

__device__ __forceinline__ void mma_bf16(float* c, const uint32_t* a, const uint32_t* b) {
    asm volatile(
        "mma.sync.aligned.m16n8k16.row.col.f32.bf16.bf16.f32 "
        "{%0,%1,%2,%3}, {%4,%5,%6,%7}, {%8,%9}, {%0,%1,%2,%3};\n"
        : "+f"(c[0]), "+f"(c[1]), "+f"(c[2]), "+f"(c[3])
        : "r"(a[0]), "r"(a[1]), "r"(a[2]), "r"(a[3]), "r"(b[0]), "r"(b[1]));
}

__device__ __forceinline__ void mma_f16(float* c, const uint32_t* a, const uint32_t* b) {
    asm volatile(
        "mma.sync.aligned.m16n8k16.row.col.f32.f16.f16.f32 "
        "{%0,%1,%2,%3}, {%4,%5,%6,%7}, {%8,%9}, {%0,%1,%2,%3};\n"
        : "+f"(c[0]), "+f"(c[1]), "+f"(c[2]), "+f"(c[3])
        : "r"(a[0]), "r"(a[1]), "r"(a[2]), "r"(a[3]), "r"(b[0]), "r"(b[1]));
}

#define LDSM4(r, a) \
    asm volatile("ldmatrix.sync.aligned.m8n8.x4.shared.b16 {%0,%1,%2,%3}, [%4];" \
        : "=r"((r)[0]), "=r"((r)[1]), "=r"((r)[2]), "=r"((r)[3]) : "r"(a))

__device__ __forceinline__ void cp16(uint32_t dst, const void* src) {
    asm volatile("cp.async.cg.shared.global [%0], [%1], 16;"
                 :: "r"(dst), "l"(src) : "memory");
}
#define CP_COMMIT() asm volatile("cp.async.commit_group;" ::: "memory")
#define CP_WAIT(n)  asm volatile("cp.async.wait_group %0;" :: "n"(n) : "memory")

// ---------------------------------------------------------------------------
// Weight prep (single launch, 112 blocks, 4 elements/thread for MLP).
// pair idx < 32768: W_v -> fp16 image; < 81920: W_so|W_aw -> bf16x3 image;
// else: W_o -> fp16 image.
// ---------------------------------------------------------------------------
__global__ void prep_all(const float* __restrict__ Wv, const float* __restrict__ Wso,
                         const float* __restrict__ Waw, const float* __restrict__ Wo,
                         char* __restrict__ ivh, char* __restrict__ iqc,
                         char* __restrict__ ioh)
{
#pragma unroll
    for (int j = 0; j < 4; j++) {
        int idx = blockIdx.x * 1024 + j * 256 + threadIdx.x;
        if (idx < 32768 || idx >= 81920) {
            // fp16 image (W_v or W_o)
            const float* W = (idx < 32768) ? Wv : Wo;
            char* img      = (idx < 32768) ? ivh : ioh;
            int id2        = (idx < 32768) ? idx : (idx - 81920);
            int n = id2 >> 7, p = id2 & 127;
            int k = p * 2;
            int kb = k >> 5, pl = (k & 31) >> 1;
            int nb = n >> 6, nl = n & 63;
            float a = W[(size_t)n * 256 + k];
            float b = W[(size_t)n * 256 + k + 1];
            char* blob = img + (size_t)(kb * 4 + nb) * 5120;
            *(uint32_t*)(blob + nl * 80 + pl * 4) = pack_f16x2(a, b);
        } else {
            int id2 = idx - 32768;      // 0..49151 (384 rows x 128 pairs)
            int n = id2 >> 7, p = id2 & 127;
            const float* Wrow = (n < 256) ? (Wso + (size_t)n * 256)
                                          : (Waw + (size_t)(n - 256) * 256);
            int k = p * 2;
            int kb = k >> 5, pl = (k & 31) >> 1;
            int nb = n >> 6, nl = n & 63;
            float a = Wrow[k];
            float b = Wrow[k + 1];
            float ah = bf_hi(a), bh = bf_hi(b);
            char* blob = iqc + (size_t)(kb * 6 + nb) * 10240;
            uint32_t off = nl * 80 + pl * 4;
            *(uint32_t*)(blob + off)        = pack_bf16x2(ah, bh);
            *(uint32_t*)(blob + 5120 + off) = pack_bf16x2(a - ah, b - bh);
        }
    }
}

// ---------------------------------------------------------------------------
// Fused independent-GEMM batch, 256 threads (8 warps 2m x 4n, warp tile 32x16).
//  bid < 680         : vproj tile 64x256 (fp16 MMA), A resident in smem,
//                      B streamed 4-deep cp.async over 32 stages (4 nb x 8 kb).
//  bid >= 680 (768)  : query tile 64x64 (bf16x3).
// ---------------------------------------------------------------------------
#define NV_BLK 680    // 43520/64
#define NQ_BLK 768    // (8192/64) * 6

__global__ void __launch_bounds__(256)
gemm_all(const float* __restrict__ values, const char* __restrict__ wvh,
         const float* __restrict__ b_v, __half* __restrict__ vproj,
         const float* __restrict__ query, const char* __restrict__ wqc,
         const float* __restrict__ b_so, const float* __restrict__ b_aw,
         float* __restrict__ offs, float* __restrict__ awr)
{
    __shared__ __align__(16) char sm[61440];

    const int tid = threadIdx.x, wid = tid >> 5, lane = tid & 31;
    const int g = lane >> 2, t = lane & 3;
    const int wm = (wid & 1) * 32, wn = (wid >> 1) * 16;
    const int r  = tid >> 2;
    const int q4 = tid & 3;
    const int rr16 = lane & 15;
    const int chi  = ((lane >> 4) & 1) * 16;
    const uint32_t sbase = smem_u32(sm);

    float acc[2][2][4];
#pragma unroll
    for (int i = 0; i < 2; i++)
#pragma unroll
        for (int j = 0; j < 2; j++)
#pragma unroll
            for (int c = 0; c < 4; c++) acc[i][j][c] = 0.0f;

    const int bid = blockIdx.x;

    if (bid < NV_BLK) {
        // ========== vproj: fp16 MMA, A-resident, 32 B-stages ==========
        const int m0 = bid * 64;
        const float* Ap = values + map_a_row(m0 + r) + q4 * 8;
        const uint32_t aoff = r * 80 + q4 * 16;

#pragma unroll
        for (int s = 0; s < 3; s++) {
            uint32_t bd = sbase + 40960 + s * 5120;
            const char* bs = wvh + (size_t)((s & 7) * 4 + (s >> 3)) * 5120;
            cp16(bd + tid * 16, bs + tid * 16);
            if (tid < 64) cp16(bd + (tid + 256) * 16, bs + (tid + 256) * 16);
            CP_COMMIT();
        }

#pragma unroll
        for (int kb = 0; kb < 8; kb++) {
            float4 v0 = *(const float4*)(Ap + kb * 32);
            float4 v1 = *(const float4*)(Ap + kb * 32 + 4);
            uint4 w;
            w.x = pack_f16x2(v0.x, v0.y); w.y = pack_f16x2(v0.z, v0.w);
            w.z = pack_f16x2(v1.x, v1.y); w.w = pack_f16x2(v1.z, v1.w);
            *(uint4*)(sm + kb * 5120 + aoff) = w;
        }
        __syncthreads();

        for (int s = 0; s < 32; s++) {
            const int kb = s & 7, nb = s >> 3;

            if (s < 30)      CP_WAIT(2);
            else if (s == 30) CP_WAIT(1);
            else              CP_WAIT(0);
            __syncthreads();

            if (s + 3 < 32) {
                const int s3 = s + 3;
                uint32_t bd = sbase + 40960 + (s3 & 3) * 5120;
                const char* bs = wvh + (size_t)((s3 & 7) * 4 + (s3 >> 3)) * 5120;
                cp16(bd + tid * 16, bs + tid * 16);
                if (tid < 64) cp16(bd + (tid + 256) * 16, bs + (tid + 256) * 16);
                CP_COMMIT();
            }

            const uint32_t baseA = sbase + kb * 5120;
            const uint32_t baseB = sbase + 40960 + (s & 3) * 5120;
#pragma unroll
            for (int ks = 0; ks < 2; ks++) {
                const int cb = ks * 32 + chi;
                uint32_t aH[2][4], bH[4];
#pragma unroll
                for (int fm = 0; fm < 2; fm++)
                    LDSM4(aH[fm], baseA + (wm + fm * 16 + rr16) * 80 + cb);
                LDSM4(bH, baseB + (wn + rr16) * 80 + cb);
#pragma unroll
                for (int fm = 0; fm < 2; fm++)
#pragma unroll
                    for (int fn = 0; fn < 2; fn++) {
                        uint32_t bh2[2] = {bH[fn], bH[fn + 2]};
                        mma_f16(acc[fm][fn], aH[fm], bh2);
                    }
            }

            if (kb == 7) {
                const int n0 = nb * 64;
#pragma unroll
                for (int fn = 0; fn < 2; fn++) {
                    int cn = n0 + wn + fn * 8 + t * 2;
                    float b0 = b_v[cn], b1 = b_v[cn + 1];
#pragma unroll
                    for (int fm = 0; fm < 2; fm++) {
                        int r0 = m0 + wm + fm * 16 + g;
                        *(__half2*)&vproj[(size_t)r0 * 256 + cn] =
                            __floats2half2_rn(acc[fm][fn][0] + b0, acc[fm][fn][1] + b1);
                        *(__half2*)&vproj[(size_t)(r0 + 8) * 256 + cn] =
                            __floats2half2_rn(acc[fm][fn][2] + b0, acc[fm][fn][3] + b1);
                        acc[fm][fn][0] = 0.0f; acc[fm][fn][1] = 0.0f;
                        acc[fm][fn][2] = 0.0f; acc[fm][fn][3] = 0.0f;
                    }
                }
            }
        }
        return;
    }

    // ================= query offs+awr: bf16x3 =================
    {
        const int qid = bid - NV_BLK;
        const int m0 = (qid / 6) * 64, nb = qid % 6, n0 = nb * 64;
        const float* Ap = query + (size_t)(m0 + r) * 256 + q4 * 8;
        const uint32_t aoff = r * 80 + q4 * 16;
        const char* bsrc0 = wqc + (size_t)nb * 10240;

        {
            float4 v0 = *(const float4*)(Ap);
            float4 v1 = *(const float4*)(Ap + 4);
            float xh = bf_hi(v0.x), yh = bf_hi(v0.y);
            float zh = bf_hi(v0.z), wwh = bf_hi(v0.w);
            float xh2 = bf_hi(v1.x), yh2 = bf_hi(v1.y);
            float zh2 = bf_hi(v1.z), wh2 = bf_hi(v1.w);
            uint4 wh, wl;
            wh.x = pack_bf16x2(xh, yh);   wh.y = pack_bf16x2(zh, wwh);
            wh.z = pack_bf16x2(xh2, yh2); wh.w = pack_bf16x2(zh2, wh2);
            wl.x = pack_bf16x2(v0.x - xh, v0.y - yh);
            wl.y = pack_bf16x2(v0.z - zh, v0.w - wwh);
            wl.z = pack_bf16x2(v1.x - xh2, v1.y - yh2);
            wl.w = pack_bf16x2(v1.z - zh2, v1.w - wh2);
            *(uint4*)(sm + aoff)        = wh;
            *(uint4*)(sm + 5120 + aoff) = wl;
        }
        float4 rA[2][2];
        rA[0][0] = *(const float4*)(Ap + 32);
        rA[0][1] = *(const float4*)(Ap + 36);
        rA[1][0] = *(const float4*)(Ap + 64);
        rA[1][1] = *(const float4*)(Ap + 68);
#pragma unroll
        for (int s = 0; s < 3; s++) {
            uint32_t bd = sbase + 20480 + s * 10240;
            const char* bs = bsrc0 + (size_t)s * 6 * 10240;
            cp16(bd + tid * 16, bs + tid * 16);
            cp16(bd + (tid + 256) * 16, bs + (tid + 256) * 16);
            if (tid < 128) cp16(bd + (tid + 512) * 16, bs + (tid + 512) * 16);
            CP_COMMIT();
        }

#pragma unroll
        for (int kb = 0; kb < 8; kb++) {
            if (kb < 6)      CP_WAIT(2);
            else if (kb == 6) CP_WAIT(1);
            else              CP_WAIT(0);
            __syncthreads();

            if (kb < 7) {
                float4 v0 = rA[0][0], v1 = rA[0][1];
                float xh = bf_hi(v0.x), yh = bf_hi(v0.y);
                float zh = bf_hi(v0.z), wwh = bf_hi(v0.w);
                float xh2 = bf_hi(v1.x), yh2 = bf_hi(v1.y);
                float zh2 = bf_hi(v1.z), wh2 = bf_hi(v1.w);
                uint4 wh, wl;
                wh.x = pack_bf16x2(xh, yh);   wh.y = pack_bf16x2(zh, wwh);
                wh.z = pack_bf16x2(xh2, yh2); wh.w = pack_bf16x2(zh2, wh2);
                wl.x = pack_bf16x2(v0.x - xh, v0.y - yh);
                wl.y = pack_bf16x2(v0.z - zh, v0.w - wwh);
                wl.z = pack_bf16x2(v1.x - xh2, v1.y - yh2);
                wl.w = pack_bf16x2(v1.z - zh2, v1.w - wh2);
                uint32_t ab = ((kb + 1) & 1) * 10240;
                *(uint4*)(sm + ab + aoff)        = wh;
                *(uint4*)(sm + ab + 5120 + aoff) = wl;
                rA[0][0] = rA[1][0]; rA[0][1] = rA[1][1];
                if (kb + 3 < 8) {
                    rA[1][0] = *(const float4*)(Ap + (kb + 3) * 32);
                    rA[1][1] = *(const float4*)(Ap + (kb + 3) * 32 + 4);
                }
            }
            if (kb + 3 < 8) {
                uint32_t bd = sbase + 20480 + ((kb + 3) & 3) * 10240;
                const char* bs = bsrc0 + (size_t)(kb + 3) * 6 * 10240;
                cp16(bd + tid * 16, bs + tid * 16);
                cp16(bd + (tid + 256) * 16, bs + (tid + 256) * 16);
                if (tid < 128) cp16(bd + (tid + 512) * 16, bs + (tid + 512) * 16);
                CP_COMMIT();
            }

            const uint32_t baseA = sbase + (kb & 1) * 10240;
            const uint32_t baseB = sbase + 20480 + (kb & 3) * 10240;
#pragma unroll
            for (int ks = 0; ks < 2; ks++) {
                const int cb = ks * 32 + chi;
                uint32_t aH[2][4], aL[2][4], bH[4], bL[4];
#pragma unroll
                for (int fm = 0; fm < 2; fm++) {
                    uint32_t ad = baseA + (wm + fm * 16 + rr16) * 80 + cb;
                    LDSM4(aH[fm], ad);
                    LDSM4(aL[fm], ad + 5120);
                }
                {
                    uint32_t bd = baseB + (wn + rr16) * 80 + cb;
                    LDSM4(bH, bd);
                    LDSM4(bL, bd + 5120);
                }
#pragma unroll
                for (int fm = 0; fm < 2; fm++)
#pragma unroll
                    for (int fn = 0; fn < 2; fn++) {
                        uint32_t bh2[2] = {bH[fn], bH[fn + 2]};
                        uint32_t bl2[2] = {bL[fn], bL[fn + 2]};
                        mma_bf16(acc[fm][fn], aL[fm], bh2);
                        mma_bf16(acc[fm][fn], aH[fm], bl2);
                        mma_bf16(acc[fm][fn], aH[fm], bh2);
                    }
            }
        }

        const bool is_aw = (n0 >= 256);
        const float* bias = is_aw ? b_aw : b_so;
        float* Cm = is_aw ? awr : offs;
        const int Nout = is_aw ? 128 : 256;
        const int ncol0 = is_aw ? (n0 - 256) : n0;
#pragma unroll
        for (int fn = 0; fn < 2; fn++) {
            int cn = ncol0 + wn + fn * 8 + t * 2;
            float b0 = bias[cn], b1 = bias[cn + 1];
#pragma unroll
            for (int fm = 0; fm < 2; fm++) {
                int r0 = m0 + wm + fm * 16 + g;
                *(float2*)&Cm[(size_t)r0 * Nout + cn] =
                    make_float2(acc[fm][fn][0] + b0, acc[fm][fn][1] + b1);
                *(float2*)&Cm[(size_t)(r0 + 8) * Nout + cn] =
                    make_float2(acc[fm][fn][2] + b0, acc[fm][fn][3] + b1);
            }
        }
    }
}

// ---------------------------------------------------------------------------
// out-proj GEMM: fp16 MMA, 128x64 tile, pure 4-stage cp.async.
//   out[128 x 64] = agg[128 x 256] @ Wo[64 x 256]^T + b_o  (fp32 out)
// 8 warps as 4(m) x 2(n), warp tile 32x32.
// stage (15360B): A@0 (128 x 80), B@10240 (64 x 80). 4 stages = 60KB.
// ---------------------------------------------------------------------------
__global__ void __launch_bounds__(256)
gemm_out(const __half* __restrict__ A, const char* __restrict__ Bimg,
         const float* __restrict__ bias, float* __restrict__ Cm)
{
    __shared__ __align__(16) char sm[61440];

    const int tid = threadIdx.x, wid = tid >> 5, lane = tid & 31;
    const int g = lane >> 2, t = lane & 3;
    const int m0 = blockIdx.x * 128, n0 = blockIdx.y * 64;
    const int wm = (wid & 3) * 32, wn = (wid >> 2) * 32;
    const int r  = tid >> 1;          // A copy: 2 threads per row, 32B each
    const int q2 = tid & 1;
    const int rr16 = lane & 15;
    const int chi  = ((lane >> 4) & 1) * 16;
    const uint32_t sbase = smem_u32(sm);

    const char* asrc = (const char*)(A + (size_t)(m0 + r) * 256) + q2 * 32;
    const char* bsrc0 = Bimg + (size_t)blockIdx.y * 5120;
    const uint32_t aoff = r * 80 + q2 * 32;

    float acc[2][4][4];
#pragma unroll
    for (int i = 0; i < 2; i++)
#pragma unroll
        for (int j = 0; j < 4; j++)
#pragma unroll
            for (int c = 0; c < 4; c++) acc[i][j][c] = 0.0f;

#pragma unroll
    for (int s = 0; s < 3; s++) {
        uint32_t sb = sbase + s * 15360;
        cp16(sb + aoff,      asrc + (size_t)s * 64);
        cp16(sb + aoff + 16, asrc + (size_t)s * 64 + 16);
        uint32_t bd = sb + 10240;
        const char* bs = bsrc0 + (size_t)s * 4 * 5120;
        cp16(bd + tid * 16, bs + tid * 16);
        if (tid < 64) cp16(bd + (tid + 256) * 16, bs + (tid + 256) * 16);
        CP_COMMIT();
    }

#pragma unroll
    for (int kb = 0; kb < 8; kb++) {
        if (kb < 6)      CP_WAIT(2);
        else if (kb == 6) CP_WAIT(1);
        else              CP_WAIT(0);
        __syncthreads();

        if (kb + 3 < 8) {
            uint32_t sb = sbase + ((kb + 3) & 3) * 15360;
            cp16(sb + aoff,      asrc + (size_t)(kb + 3) * 64);
            cp16(sb + aoff + 16, asrc + (size_t)(kb + 3) * 64 + 16);
            uint32_t bd = sb + 10240;
            const char* bs = bsrc0 + (size_t)(kb + 3) * 4 * 5120;
            cp16(bd + tid * 16, bs + tid * 16);
            if (tid < 64) cp16(bd + (tid + 256) * 16, bs + (tid + 256) * 16);
            CP_COMMIT();
        }

        const uint32_t base = sbase + (kb & 3) * 15360;
#pragma unroll
        for (int ks = 0; ks < 2; ks++) {
            const int cb = ks * 32 + chi;
            uint32_t aH[2][4], bH[2][4];
#pragma unroll
            for (int fm = 0; fm < 2; fm++)
                LDSM4(aH[fm], base + (wm + fm * 16 + rr16) * 80 + cb);
#pragma unroll
            for (int fp = 0; fp < 2; fp++)
                LDSM4(bH[fp], base + 10240 + (wn + fp * 16 + rr16) * 80 + cb);
#pragma unroll
            for (int fm = 0; fm < 2; fm++)
#pragma unroll
                for (int fn = 0; fn < 4; fn++) {
                    const int fp = fn >> 1, o = fn & 1;
                    uint32_t bh2[2] = {bH[fp][o], bH[fp][o + 2]};
                    mma_f16(acc[fm][fn], aH[fm], bh2);
                }
        }
    }

#pragma unroll
    for (int fn = 0; fn < 4; fn++) {
        int cn = n0 + wn + fn * 8 + t * 2;
        float b0 = bias[cn], b1 = bias[cn + 1];
#pragma unroll
        for (int fm = 0; fm < 2; fm++) {
            int r0 = m0 + wm + fm * 16 + g;
            *(float2*)&Cm[(size_t)r0 * 256 + cn] =
                make_float2(acc[fm][fn][0] + b0, acc[fm][fn][1] + b1);
            *(float2*)&Cm[(size_t)(r0 + 8) * 256 + cn] =
                make_float2(acc[fm][fn][2] + b0, acc[fm][fn][3] + b1);
        }
    }
}

// ---------------------------------------------------------------------------
// Sampling kernel: 8 queries per block (256 threads); 16B vectorized gathers.
// ---------------------------------------------------------------------------
#define QPB 8
__global__ __launch_bounds__(256)
void sample_kernel(const float* __restrict__ ref,
                   const int* __restrict__ batch_offsets)
{
    __shared__ float sL[QPB][128];
    __shared__ float hM[QPB][8];
    __shared__ float hR[QPB][8];
    __shared__ float sIS[QPB][2];
    __shared__ __align__(16) int   srow[QPB][128][4];
    __shared__ __align__(16) float swt [QPB][128][4];

    const int tid = threadIdx.x;
    const int q0  = blockIdx.x * QPB;
    const int boundary = batch_offsets[1];

#pragma unroll
    for (int j = tid; j < QPB * 128; j += 256)
        sL[j >> 7][j & 127] = g_awr[(size_t)(q0 + (j >> 7)) * 128 + (j & 127)];

    if (tid >= 224 && tid < 224 + QPB * 2) {
        int k = tid - 224;
        int qi = k >> 1, xy = k & 1;
        float v = ref[(q0 + qi) * 2 + xy];
        v = fminf(fmaxf(v, 0.0f), 1.0f);
        sIS[qi][xy] = logf(fmaxf(v, 1e-5f) / fmaxf(1.0f - v, 1e-5f));
    }
    __syncthreads();

    if (tid < QPB * 8) {
        int qi = tid >> 3, h = tid & 7;
        float m = -1e30f;
#pragma unroll
        for (int lp = 0; lp < 16; lp++) m = fmaxf(m, sL[qi][lp * 8 + h]);
        float s = 0.0f;
#pragma unroll
        for (int lp = 0; lp < 16; lp++) s += expf(sL[qi][lp * 8 + h] - m);
        hM[qi][h] = m;
        hR[qi][h] = 1.0f / s;
    }
    __syncthreads();

#pragma unroll
    for (int j = tid; j < QPB * 128; j += 256) {
        const int qi = j >> 7;
        const int i  = j & 127;
        const int q  = q0 + qi;
        const int h  = i & 7;
        const int lp = i >> 3;
        const int l  = lp >> 2;

        float aw = expf(sL[qi][i] - hM[qi][h]) * hR[qi][h];

        float ox = g_offs[(size_t)q * 256 + i * 2 + 0];
        float oy = g_offs[(size_t)q * 256 + i * 2 + 1];

        float locx = 1.0f / (1.0f + expf(-(sIS[qi][0] + ox)));
        float locy = 1.0f / (1.0f + expf(-(sIS[qi][1] + oy)));

        const int   Wl = HMAX_ >> l;
        const float Wf = (float)Wl;
        float x = locx * Wf - 0.5f;
        float y = locy * Wf - 0.5f;

        float x0f = floorf(x), y0f = floorf(y);
        float wx1 = x - x0f, wx0 = 1.0f - wx1;
        float wy1 = y - y0f, wy0 = 1.0f - wy1;
        int x0 = (int)x0f, y0 = (int)y0f;

        int b = (q >= boundary) ? 1 : 0;
        int lbase = (l >= 1 ? 16384 : 0) + (l >= 2 ? 4096 : 0) + (l >= 3 ? 1024 : 0);
        int base = b * ROWS_PER_B + lbase;

        int   xs[2]  = {x0, x0 + 1};
        int   ys2[2] = {y0, y0 + 1};
        float wxs[2] = {wx0, wx1};
        float wys[2] = {wy0, wy1};

#pragma unroll
        for (int cy = 0; cy < 2; cy++) {
#pragma unroll
            for (int cx = 0; cx < 2; cx++) {
                int c  = cy * 2 + cx;
                int xi = xs[cx], yi = ys2[cy];
                bool valid = (xi >= 0) & (xi < Wl) & (yi >= 0) & (yi < Wl);
                int xc = min(max(xi, 0), Wl - 1);
                int yc = min(max(yi, 0), Wl - 1);
                srow[qi][i][c] = base + yc * Wl + xc;
                swt [qi][i][c] = valid ? (aw * wys[cy] * wxs[cx]) : 0.0f;
            }
        }
    }
    __syncthreads();

    // gather: 32 threads per query, 8 channels each (16B loads)
    const int qi   = tid >> 5;
    const int tq   = tid & 31;
    const int h    = tq >> 2;
    const int coff = h * DH_ + (tq & 3) * 8;
    const int q    = q0 + qi;

    float acc[8];
#pragma unroll
    for (int e = 0; e < 8; e++) acc[e] = 0.0f;

#pragma unroll
    for (int lp = 0; lp < 16; lp++) {
        const int i = lp * 8 + h;
        int4   r4 = *(const int4*)  &srow[qi][i][0];
        float4 w4 = *(const float4*)&swt [qi][i][0];
        int   rr[4] = {r4.x, r4.y, r4.z, r4.w};
        float ww[4] = {w4.x, w4.y, w4.z, w4.w};
#pragma unroll
        for (int c = 0; c < 4; c++) {
            const uint4 v = __ldg((const uint4*)&g_vproj[(size_t)rr[c] * C_ + coff]);
            const __half2* hp = (const __half2*)&v;
            float w = ww[c];
#pragma unroll
            for (int e = 0; e < 4; e++) {
                float2 f = __half22float2(hp[e]);
                acc[e * 2 + 0] += w * f.x;
                acc[e * 2 + 1] += w * f.y;
            }
        }
    }
    uint4 outv;
    outv.x = pack_f16x2(acc[0], acc[1]);
    outv.y = pack_f16x2(acc[2], acc[3]);
    outv.z = pack_f16x2(acc[4], acc[5]);
    outv.w = pack_f16x2(acc[6], acc[7]);
    *(uint4*)&g_agg[(size_t)q * C_ + coff] = outv;
}

// ---------------------------------------------------------------------------
// kernel_launch
// ---------------------------------------------------------------------------
extern "C" void kernel_launch(void* const* d_in, const int* in_sizes, int n_in,
                              void* d_out, int out_size)
{
    const float* query  = (const float*)d_in[0];
    const float* ref    = (const float*)d_in[1];
    const float* values = (const float*)d_in[2];
    const float* W_so   = (const float*)d_in[3];
    const float* b_so   = (const float*)d_in[4];
    const float* W_aw   = (const float*)d_in[5];
    const float* b_aw   = (const float*)d_in[6];
    const float* W_v    = (const float*)d_in[7];
    const float* b_v    = (const float*)d_in[8];
    const float* W_o    = (const float*)d_in[9];
    const float* b_o    = (const float*)d_in[10];
    const int* batch_offsets = (const int*)d_in[11];
    float* out = (float*)d_out;
    (void)in_sizes; (void)n_in; (void)out_size;

    __half *vproj, *agg;
    float *offs, *awr;
    char *wvh, *wqc, *woh;
    cudaGetSymbolAddress((void**)&vproj, g_vproj);
    cudaGetSymbolAddress((void**)&offs,  g_offs);
    cudaGetSymbolAddress((void**)&awr,   g_awr);
    cudaGetSymbolAddress((void**)&agg,   g_agg);
    cudaGetSymbolAddress((void**)&wvh,   g_wvh_img);
    cudaGetSymbolAddress((void**)&wqc,   g_wqc_img);
    cudaGetSymbolAddress((void**)&woh,   g_woh_img);

    // 0) weight images (single launch, 4 elems/thread)
    prep_all<<<112, 256>>>(W_v, W_so, W_aw, W_o, wvh, wqc, woh);

    // 1) vproj + offs + awr, one fused launch (1448 CTAs, 8 warps each)
    gemm_all<<<NV_BLK + NQ_BLK, 256>>>(values, wvh, b_v, vproj,
                                       query, wqc, b_so, b_aw, offs, awr);

    // 2) softmax + bilinear sampling + head aggregation (fp16 agg out)
    sample_kernel<<<Q_ / QPB, 256>>>(ref, batch_offsets);

    // 3) out = agg @ W_o^T + b_o  [8192 x 256] (fp16 MMA, 128x64 tiles)
    {
        dim3 grid(Q_ / 128, 4);
        gemm_out<<<grid, 256>>>(agg, woh, b_o, out);
    }
}

// round 17
// speedup vs baseline: 1.0093x; 1.0093x over previous
#include <cuda_runtime.h>
#include <cuda_bf16.h>
#include <cuda_fp16.h>
#include <cstdint>
#include <cstddef>

// ---------------------------------------------------------------------------
// Problem constants (fixed by the dataset)
// ---------------------------------------------------------------------------
#define Q_   8192
#define C_   256
#define LVL  4
#define NH_  8
#define DH_  32
#define HMAX_ 128

#define ROWS_PER_B 21760   // 16384+4096+1024+256
#define NROWS      43520   // 2 * ROWS_PER_B

// ---------------------------------------------------------------------------
// Scratch (device globals; no allocation allowed)
// ---------------------------------------------------------------------------
__device__ __half g_vproj[(size_t)NROWS * C_];  // projected valid values (fp16)
__device__ float  g_offs [(size_t)Q_ * 256];    // sampling-offset raw proj
__device__ float  g_awr  [(size_t)Q_ * 128];    // attention-weight logits
__device__ __half g_agg  [(size_t)Q_ * C_];     // per-query aggregated heads (fp16)

// bf16x3 weight image (combined W_so|W_aw): per (kb32, nb64): [hi 5120B | lo 5120B]
__device__ __align__(16) char g_wqc_img[491520];   // 384 rows: 8 kb x 6 nb x 10240
// fp16 weight images: per (kb, nb64) blob: 5120B (fp16x2 pairs)
__device__ __align__(16) char g_wvh_img[163840];   // W_v: 8 kb x 4 nb x 5120
__device__ __align__(16) char g_woh_img[163840];   // W_o: 8 kb x 4 nb x 5120

// ---------------------------------------------------------------------------
// Row mapping: compact row r -> offset into values[B,128,128,L,C]
// ---------------------------------------------------------------------------
__device__ __forceinline__ size_t map_a_row(int r) {
    int b  = r / ROWS_PER_B;
    int rr = r - b * ROWS_PER_B;
    int l, base, W;
    if (rr < 16384)      { l = 0; base = 0;     W = 128; }
    else if (rr < 20480) { l = 1; base = 16384; W = 64;  }
    else if (rr < 21504) { l = 2; base = 20480; W = 32;  }
    else                 { l = 3; base = 21504; W = 16;  }
    int idx = rr - base;
    int y = idx / W;
    int x = idx - y * W;
    return ((((size_t)b * HMAX_ + y) * HMAX_ + x) * LVL + l) * C_;
}

// ---------------------------------------------------------------------------
// helpers
// ---------------------------------------------------------------------------
__device__ __forceinline__ uint32_t smem_u32(const void* p) {
    uint32_t a;
    asm("{ .reg .u64 t; cvta.to.shared.u64 t, %1; cvt.u32.u64 %0, t; }"
        : "=r"(a) : "l"(p));
    return a;
}

__device__ __forceinline__ uint32_t pack_bf16x2(float e0, float e1) {
    uint32_t r;
    asm("cvt.rn.bf16x2.f32 %0, %1, %2;" : "=r"(r) : "f"(e1), "f"(e0));
    return r;
}

__device__ __forceinline__ uint32_t pack_f16x2(float e0, float e1) {
    uint32_t r;
    asm("cvt.rn.f16x2.f32 %0, %1, %2;" : "=r"(r) : "f"(e1), "f"(e0));
    return r;
}

__device__ __forceinline__ float bf_hi(float x) {
    return __bfloat162float(__float2bfloat16_rn(x));
}

__device__ __forceinline__ void mma_bf16(float* c, const uint32_t* a, const uint32_t* b) {
    asm volatile(
        "mma.sync.aligned.m16n8k16.row.col.f32.bf16.bf16.f32 "
        "{%0,%1,%2,%3}, {%4,%5,%6,%7}, {%8,%9}, {%0,%1,%2,%3};\n"
        : "+f"(c[0]), "+f"(c[1]), "+f"(c[2]), "+f"(c[3])
        : "r"(a[0]), "r"(a[1]), "r"(a[2]), "r"(a[3]), "r"(b[0]), "r"(b[1]));
}

__device__ __forceinline__ void mma_f16(float* c, const uint32_t* a, const uint32_t* b) {
    asm volatile(
        "mma.sync.aligned.m16n8k16.row.col.f32.f16.f16.f32 "
        "{%0,%1,%2,%3}, {%4,%5,%6,%7}, {%8,%9}, {%0,%1,%2,%3};\n"
        : "+f"(c[0]), "+f"(c[1]), "+f"(c[2]), "+f"(c[3])
        : "r"(a[0]), "r"(a[1]), "r"(a[2]), "r"(a[3]), "r"(b[0]), "r"(b[1]));
}

#define LDSM4(r, a) \
    asm volatile("ldmatrix.sync.aligned.m8n8.x4.shared.b16 {%0,%1,%2,%3}, [%4];" \
        : "=r"((r)[0]), "=r"((r)[1]), "=r"((r)[2]), "=r"((r)[3]) : "r"(a))

__device__ __forceinline__ void cp16(uint32_t dst, const void* src) {
    asm volatile("cp.async.cg.shared.global [%0], [%1], 16;"
                 :: "r"(dst), "l"(src) : "memory");
}
#define CP_COMMIT() asm volatile("cp.async.commit_group;" ::: "memory")
#define CP_WAIT(n)  asm volatile("cp.async.wait_group %0;" :: "n"(n) : "memory")

// ---------------------------------------------------------------------------
// Weight prep (single launch) — round-15 configuration.
// blocks 0-127:   W_v -> fp16 image (256 rows)
// blocks 128-319: W_so|W_aw combined -> bf16x3 image (384 rows)
// blocks 320-447: W_o -> fp16 image (256 rows)
// ---------------------------------------------------------------------------
__global__ void prep_all(const float* __restrict__ Wv, const float* __restrict__ Wso,
                         const float* __restrict__ Waw, const float* __restrict__ Wo,
                         char* __restrict__ ivh, char* __restrict__ iqc,
                         char* __restrict__ ioh)
{
    int blk = blockIdx.x;
    if (blk < 128 || blk >= 320) {
        const float* W = (blk < 128) ? Wv : Wo;
        char* img      = (blk < 128) ? ivh : ioh;
        int lb         = (blk < 128) ? blk : (blk - 320);
        int idx = lb * 256 + threadIdx.x;
        int n = idx >> 7, p = idx & 127;
        int k = p * 2;
        int kb = k >> 5, pl = (k & 31) >> 1;
        int nb = n >> 6, nl = n & 63;
        float a = W[(size_t)n * 256 + k];
        float b = W[(size_t)n * 256 + k + 1];
        char* blob = img + (size_t)(kb * 4 + nb) * 5120;
        *(uint32_t*)(blob + nl * 80 + pl * 4) = pack_f16x2(a, b);
        return;
    }
    int idx = (blk - 128) * 256 + threadIdx.x;
    int n = idx >> 7, p = idx & 127;
    const float* Wrow = (n < 256) ? (Wso + (size_t)n * 256) : (Waw + (size_t)(n - 256) * 256);
    int k = p * 2;
    int kb = k >> 5, pl = (k & 31) >> 1;
    int nb = n >> 6, nl = n & 63;
    float a = Wrow[k];
    float b = Wrow[k + 1];
    float ah = bf_hi(a), bh = bf_hi(b);
    char* blob = iqc + (size_t)(kb * 6 + nb) * 10240;
    uint32_t off = nl * 80 + pl * 4;
    *(uint32_t*)(blob + off)        = pack_bf16x2(ah, bh);
    *(uint32_t*)(blob + 5120 + off) = pack_bf16x2(a - ah, b - bh);
}

// ---------------------------------------------------------------------------
// Fused independent-GEMM batch (round-15), 256 threads (8 warps 2m x 4n).
//  bid < 680         : vproj tile 64x256 (fp16 MMA), A resident,
//                      B streamed 4-deep cp.async over 32 stages.
//  bid >= 680 (768)  : query tile 64x64 (bf16x3).
// ---------------------------------------------------------------------------
#define NV_BLK 680    // 43520/64
#define NQ_BLK 768    // (8192/64) * 6

__global__ void __launch_bounds__(256)
gemm_all(const float* __restrict__ values, const char* __restrict__ wvh,
         const float* __restrict__ b_v, __half* __restrict__ vproj,
         const float* __restrict__ query, const char* __restrict__ wqc,
         const float* __restrict__ b_so, const float* __restrict__ b_aw,
         float* __restrict__ offs, float* __restrict__ awr)
{
    __shared__ __align__(16) char sm[61440];

    const int tid = threadIdx.x, wid = tid >> 5, lane = tid & 31;
    const int g = lane >> 2, t = lane & 3;
    const int wm = (wid & 1) * 32, wn = (wid >> 1) * 16;
    const int r  = tid >> 2;
    const int q4 = tid & 3;
    const int rr16 = lane & 15;
    const int chi  = ((lane >> 4) & 1) * 16;
    const uint32_t sbase = smem_u32(sm);

    float acc[2][2][4];
#pragma unroll
    for (int i = 0; i < 2; i++)
#pragma unroll
        for (int j = 0; j < 2; j++)
#pragma unroll
            for (int c = 0; c < 4; c++) acc[i][j][c] = 0.0f;

    const int bid = blockIdx.x;

    if (bid < NV_BLK) {
        // ========== vproj: fp16 MMA, A-resident, 32 B-stages ==========
        const int m0 = bid * 64;
        const float* Ap = values + map_a_row(m0 + r) + q4 * 8;
        const uint32_t aoff = r * 80 + q4 * 16;

#pragma unroll
        for (int s = 0; s < 3; s++) {
            uint32_t bd = sbase + 40960 + s * 5120;
            const char* bs = wvh + (size_t)((s & 7) * 4 + (s >> 3)) * 5120;
            cp16(bd + tid * 16, bs + tid * 16);
            if (tid < 64) cp16(bd + (tid + 256) * 16, bs + (tid + 256) * 16);
            CP_COMMIT();
        }

#pragma unroll
        for (int kb = 0; kb < 8; kb++) {
            float4 v0 = *(const float4*)(Ap + kb * 32);
            float4 v1 = *(const float4*)(Ap + kb * 32 + 4);
            uint4 w;
            w.x = pack_f16x2(v0.x, v0.y); w.y = pack_f16x2(v0.z, v0.w);
            w.z = pack_f16x2(v1.x, v1.y); w.w = pack_f16x2(v1.z, v1.w);
            *(uint4*)(sm + kb * 5120 + aoff) = w;
        }
        __syncthreads();

        for (int s = 0; s < 32; s++) {
            const int kb = s & 7, nb = s >> 3;

            if (s < 30)      CP_WAIT(2);
            else if (s == 30) CP_WAIT(1);
            else              CP_WAIT(0);
            __syncthreads();

            if (s + 3 < 32) {
                const int s3 = s + 3;
                uint32_t bd = sbase + 40960 + (s3 & 3) * 5120;
                const char* bs = wvh + (size_t)((s3 & 7) * 4 + (s3 >> 3)) * 5120;
                cp16(bd + tid * 16, bs + tid * 16);
                if (tid < 64) cp16(bd + (tid + 256) * 16, bs + (tid + 256) * 16);
                CP_COMMIT();
            }

            const uint32_t baseA = sbase + kb * 5120;
            const uint32_t baseB = sbase + 40960 + (s & 3) * 5120;
#pragma unroll
            for (int ks = 0; ks < 2; ks++) {
                const int cb = ks * 32 + chi;
                uint32_t aH[2][4], bH[4];
#pragma unroll
                for (int fm = 0; fm < 2; fm++)
                    LDSM4(aH[fm], baseA + (wm + fm * 16 + rr16) * 80 + cb);
                LDSM4(bH, baseB + (wn + rr16) * 80 + cb);
#pragma unroll
                for (int fm = 0; fm < 2; fm++)
#pragma unroll
                    for (int fn = 0; fn < 2; fn++) {
                        uint32_t bh2[2] = {bH[fn], bH[fn + 2]};
                        mma_f16(acc[fm][fn], aH[fm], bh2);
                    }
            }

            if (kb == 7) {
                const int n0 = nb * 64;
#pragma unroll
                for (int fn = 0; fn < 2; fn++) {
                    int cn = n0 + wn + fn * 8 + t * 2;
                    float b0 = b_v[cn], b1 = b_v[cn + 1];
#pragma unroll
                    for (int fm = 0; fm < 2; fm++) {
                        int r0 = m0 + wm + fm * 16 + g;
                        *(__half2*)&vproj[(size_t)r0 * 256 + cn] =
                            __floats2half2_rn(acc[fm][fn][0] + b0, acc[fm][fn][1] + b1);
                        *(__half2*)&vproj[(size_t)(r0 + 8) * 256 + cn] =
                            __floats2half2_rn(acc[fm][fn][2] + b0, acc[fm][fn][3] + b1);
                        acc[fm][fn][0] = 0.0f; acc[fm][fn][1] = 0.0f;
                        acc[fm][fn][2] = 0.0f; acc[fm][fn][3] = 0.0f;
                    }
                }
            }
        }
        return;
    }

    // ================= query offs+awr: bf16x3 =================
    {
        const int qid = bid - NV_BLK;
        const int m0 = (qid / 6) * 64, nb = qid % 6, n0 = nb * 64;
        const float* Ap = query + (size_t)(m0 + r) * 256 + q4 * 8;
        const uint32_t aoff = r * 80 + q4 * 16;
        const char* bsrc0 = wqc + (size_t)nb * 10240;

        {
            float4 v0 = *(const float4*)(Ap);
            float4 v1 = *(const float4*)(Ap + 4);
            float xh = bf_hi(v0.x), yh = bf_hi(v0.y);
            float zh = bf_hi(v0.z), wwh = bf_hi(v0.w);
            float xh2 = bf_hi(v1.x), yh2 = bf_hi(v1.y);
            float zh2 = bf_hi(v1.z), wh2 = bf_hi(v1.w);
            uint4 wh, wl;
            wh.x = pack_bf16x2(xh, yh);   wh.y = pack_bf16x2(zh, wwh);
            wh.z = pack_bf16x2(xh2, yh2); wh.w = pack_bf16x2(zh2, wh2);
            wl.x = pack_bf16x2(v0.x - xh, v0.y - yh);
            wl.y = pack_bf16x2(v0.z - zh, v0.w - wwh);
            wl.z = pack_bf16x2(v1.x - xh2, v1.y - yh2);
            wl.w = pack_bf16x2(v1.z - zh2, v1.w - wh2);
            *(uint4*)(sm + aoff)        = wh;
            *(uint4*)(sm + 5120 + aoff) = wl;
        }
        float4 rA[2][2];
        rA[0][0] = *(const float4*)(Ap + 32);
        rA[0][1] = *(const float4*)(Ap + 36);
        rA[1][0] = *(const float4*)(Ap + 64);
        rA[1][1] = *(const float4*)(Ap + 68);
#pragma unroll
        for (int s = 0; s < 3; s++) {
            uint32_t bd = sbase + 20480 + s * 10240;
            const char* bs = bsrc0 + (size_t)s * 6 * 10240;
            cp16(bd + tid * 16, bs + tid * 16);
            cp16(bd + (tid + 256) * 16, bs + (tid + 256) * 16);
            if (tid < 128) cp16(bd + (tid + 512) * 16, bs + (tid + 512) * 16);
            CP_COMMIT();
        }

#pragma unroll
        for (int kb = 0; kb < 8; kb++) {
            if (kb < 6)      CP_WAIT(2);
            else if (kb == 6) CP_WAIT(1);
            else              CP_WAIT(0);
            __syncthreads();

            if (kb < 7) {
                float4 v0 = rA[0][0], v1 = rA[0][1];
                float xh = bf_hi(v0.x), yh = bf_hi(v0.y);
                float zh = bf_hi(v0.z), wwh = bf_hi(v0.w);
                float xh2 = bf_hi(v1.x), yh2 = bf_hi(v1.y);
                float zh2 = bf_hi(v1.z), wh2 = bf_hi(v1.w);
                uint4 wh, wl;
                wh.x = pack_bf16x2(xh, yh);   wh.y = pack_bf16x2(zh, wwh);
                wh.z = pack_bf16x2(xh2, yh2); wh.w = pack_bf16x2(zh2, wh2);
                wl.x = pack_bf16x2(v0.x - xh, v0.y - yh);
                wl.y = pack_bf16x2(v0.z - zh, v0.w - wwh);
                wl.z = pack_bf16x2(v1.x - xh2, v1.y - yh2);
                wl.w = pack_bf16x2(v1.z - zh2, v1.w - wh2);
                uint32_t ab = ((kb + 1) & 1) * 10240;
                *(uint4*)(sm + ab + aoff)        = wh;
                *(uint4*)(sm + ab + 5120 + aoff) = wl;
                rA[0][0] = rA[1][0]; rA[0][1] = rA[1][1];
                if (kb + 3 < 8) {
                    rA[1][0] = *(const float4*)(Ap + (kb + 3) * 32);
                    rA[1][1] = *(const float4*)(Ap + (kb + 3) * 32 + 4);
                }
            }
            if (kb + 3 < 8) {
                uint32_t bd = sbase + 20480 + ((kb + 3) & 3) * 10240;
                const char* bs = bsrc0 + (size_t)(kb + 3) * 6 * 10240;
                cp16(bd + tid * 16, bs + tid * 16);
                cp16(bd + (tid + 256) * 16, bs + (tid + 256) * 16);
                if (tid < 128) cp16(bd + (tid + 512) * 16, bs + (tid + 512) * 16);
                CP_COMMIT();
            }

            const uint32_t baseA = sbase + (kb & 1) * 10240;
            const uint32_t baseB = sbase + 20480 + (kb & 3) * 10240;
#pragma unroll
            for (int ks = 0; ks < 2; ks++) {
                const int cb = ks * 32 + chi;
                uint32_t aH[2][4], aL[2][4], bH[4], bL[4];
#pragma unroll
                for (int fm = 0; fm < 2; fm++) {
                    uint32_t ad = baseA + (wm + fm * 16 + rr16) * 80 + cb;
                    LDSM4(aH[fm], ad);
                    LDSM4(aL[fm], ad + 5120);
                }
                {
                    uint32_t bd = baseB + (wn + rr16) * 80 + cb;
                    LDSM4(bH, bd);
                    LDSM4(bL, bd + 5120);
                }
#pragma unroll
                for (int fm = 0; fm < 2; fm++)
#pragma unroll
                    for (int fn = 0; fn < 2; fn++) {
                        uint32_t bh2[2] = {bH[fn], bH[fn + 2]};
                        uint32_t bl2[2] = {bL[fn], bL[fn + 2]};
                        mma_bf16(acc[fm][fn], aL[fm], bh2);
                        mma_bf16(acc[fm][fn], aH[fm], bl2);
                        mma_bf16(acc[fm][fn], aH[fm], bh2);
                    }
            }
        }

        const bool is_aw = (n0 >= 256);
        const float* bias = is_aw ? b_aw : b_so;
        float* Cm = is_aw ? awr : offs;
        const int Nout = is_aw ? 128 : 256;
        const int ncol0 = is_aw ? (n0 - 256) : n0;
#pragma unroll
        for (int fn = 0; fn < 2; fn++) {
            int cn = ncol0 + wn + fn * 8 + t * 2;
            float b0 = bias[cn], b1 = bias[cn + 1];
#pragma unroll
            for (int fm = 0; fm < 2; fm++) {
                int r0 = m0 + wm + fm * 16 + g;
                *(float2*)&Cm[(size_t)r0 * Nout + cn] =
                    make_float2(acc[fm][fn][0] + b0, acc[fm][fn][1] + b1);
                *(float2*)&Cm[(size_t)(r0 + 8) * Nout + cn] =
                    make_float2(acc[fm][fn][2] + b0, acc[fm][fn][3] + b1);
            }
        }
    }
}

// ---------------------------------------------------------------------------
// out-proj GEMM: fp16 MMA, 64x64 tile, B-RESIDENT (40KB) + A streamed 4-deep.
//   out[64 x 64] = agg[64 x 256] @ Wo[64 x 256]^T + b_o  (fp32 out)
// smem (dynamic 61440B): B resident @0 (8 kb x 5120), A ring @40960 (4 x 5120).
// ---------------------------------------------------------------------------
__global__ void __launch_bounds__(256)
gemm_out(const __half* __restrict__ A, const char* __restrict__ Bimg,
         const float* __restrict__ bias, float* __restrict__ Cm)
{
    extern __shared__ __align__(16) char sm[];

    const int tid = threadIdx.x, wid = tid >> 5, lane = tid & 31;
    const int g = lane >> 2, t = lane & 3;
    const int m0 = blockIdx.x * 64, n0 = blockIdx.y * 64;
    const int wm = (wid & 1) * 32, wn = (wid >> 1) * 16;
    const int r  = tid >> 2;
    const int q4 = tid & 3;
    const int rr16 = lane & 15;
    const int chi  = ((lane >> 4) & 1) * 16;
    const uint32_t sbase = smem_u32(sm);

    const char* asrc = (const char*)(A + (size_t)(m0 + r) * 256) + q4 * 16;
    const char* bsrc0 = Bimg + (size_t)blockIdx.y * 5120;   // nb blob for kb=0
    const uint32_t aoff = r * 80 + q4 * 16;

    float acc[2][2][4];
#pragma unroll
    for (int i = 0; i < 2; i++)
#pragma unroll
        for (int j = 0; j < 2; j++)
#pragma unroll
            for (int c = 0; c < 4; c++) acc[i][j][c] = 0.0f;

    // B resident: 8 kb-blobs of 5120B -> 40960B at smem offset kb*5120.
    // 2560 cp16 over 256 threads = 10 each. One commit group (oldest).
#pragma unroll
    for (int j = 0; j < 10; j++) {
        int idx = tid + 256 * j;              // 0..2559
        int kb = idx / 320, e = idx % 320;    // 320 x 16B per blob
        cp16(sbase + kb * 5120 + e * 16, bsrc0 + (size_t)kb * 4 * 5120 + e * 16);
    }
    CP_COMMIT();

    // A stages 0..2
#pragma unroll
    for (int s = 0; s < 3; s++) {
        cp16(sbase + 40960 + s * 5120 + aoff, asrc + (size_t)s * 64);
        CP_COMMIT();
    }

#pragma unroll
    for (int kb = 0; kb < 8; kb++) {
        // pending groups after prologue: B, A0, A1, A2. WAIT(2) at kb=0 drains
        // B+A0; steady state keeps 2 A-stages in flight.
        if (kb < 6)      CP_WAIT(2);
        else if (kb == 6) CP_WAIT(1);
        else              CP_WAIT(0);
        __syncthreads();

        if (kb + 3 < 8) {
            cp16(sbase + 40960 + ((kb + 3) & 3) * 5120 + aoff,
                 asrc + (size_t)(kb + 3) * 64);
            CP_COMMIT();
        }

        const uint32_t baseA = sbase + 40960 + (kb & 3) * 5120;
        const uint32_t baseB = sbase + kb * 5120;
#pragma unroll
        for (int ks = 0; ks < 2; ks++) {
            const int cb = ks * 32 + chi;
            uint32_t aH[2][4], bH[4];
#pragma unroll
            for (int fm = 0; fm < 2; fm++)
                LDSM4(aH[fm], baseA + (wm + fm * 16 + rr16) * 80 + cb);
            LDSM4(bH, baseB + (wn + rr16) * 80 + cb);
#pragma unroll
            for (int fm = 0; fm < 2; fm++)
#pragma unroll
                for (int fn = 0; fn < 2; fn++) {
                    uint32_t bh2[2] = {bH[fn], bH[fn + 2]};
                    mma_f16(acc[fm][fn], aH[fm], bh2);
                }
        }
    }

#pragma unroll
    for (int fn = 0; fn < 2; fn++) {
        int cn = n0 + wn + fn * 8 + t * 2;
        float b0 = bias[cn], b1 = bias[cn + 1];
#pragma unroll
        for (int fm = 0; fm < 2; fm++) {
            int r0 = m0 + wm + fm * 16 + g;
            *(float2*)&Cm[(size_t)r0 * 256 + cn] =
                make_float2(acc[fm][fn][0] + b0, acc[fm][fn][1] + b1);
            *(float2*)&Cm[(size_t)(r0 + 8) * 256 + cn] =
                make_float2(acc[fm][fn][2] + b0, acc[fm][fn][3] + b1);
        }
    }
}

// ---------------------------------------------------------------------------
// Sampling kernel: 8 queries per block (256 threads); 16B vectorized gathers.
// ---------------------------------------------------------------------------
#define QPB 8
__global__ __launch_bounds__(256)
void sample_kernel(const float* __restrict__ ref,
                   const int* __restrict__ batch_offsets)
{
    __shared__ float sL[QPB][128];
    __shared__ float hM[QPB][8];
    __shared__ float hR[QPB][8];
    __shared__ float sIS[QPB][2];
    __shared__ __align__(16) int   srow[QPB][128][4];
    __shared__ __align__(16) float swt [QPB][128][4];

    const int tid = threadIdx.x;
    const int q0  = blockIdx.x * QPB;
    const int boundary = batch_offsets[1];

#pragma unroll
    for (int j = tid; j < QPB * 128; j += 256)
        sL[j >> 7][j & 127] = g_awr[(size_t)(q0 + (j >> 7)) * 128 + (j & 127)];

    if (tid >= 224 && tid < 224 + QPB * 2) {
        int k = tid - 224;
        int qi = k >> 1, xy = k & 1;
        float v = ref[(q0 + qi) * 2 + xy];
        v = fminf(fmaxf(v, 0.0f), 1.0f);
        sIS[qi][xy] = logf(fmaxf(v, 1e-5f) / fmaxf(1.0f - v, 1e-5f));
    }
    __syncthreads();

    if (tid < QPB * 8) {
        int qi = tid >> 3, h = tid & 7;
        float m = -1e30f;
#pragma unroll
        for (int lp = 0; lp < 16; lp++) m = fmaxf(m, sL[qi][lp * 8 + h]);
        float s = 0.0f;
#pragma unroll
        for (int lp = 0; lp < 16; lp++) s += expf(sL[qi][lp * 8 + h] - m);
        hM[qi][h] = m;
        hR[qi][h] = 1.0f / s;
    }
    __syncthreads();

#pragma unroll
    for (int j = tid; j < QPB * 128; j += 256) {
        const int qi = j >> 7;
        const int i  = j & 127;
        const int q  = q0 + qi;
        const int h  = i & 7;
        const int lp = i >> 3;
        const int l  = lp >> 2;

        float aw = expf(sL[qi][i] - hM[qi][h]) * hR[qi][h];

        float ox = g_offs[(size_t)q * 256 + i * 2 + 0];
        float oy = g_offs[(size_t)q * 256 + i * 2 + 1];

        float locx = 1.0f / (1.0f + expf(-(sIS[qi][0] + ox)));
        float locy = 1.0f / (1.0f + expf(-(sIS[qi][1] + oy)));

        const int   Wl = HMAX_ >> l;
        const float Wf = (float)Wl;
        float x = locx * Wf - 0.5f;
        float y = locy * Wf - 0.5f;

        float x0f = floorf(x), y0f = floorf(y);
        float wx1 = x - x0f, wx0 = 1.0f - wx1;
        float wy1 = y - y0f, wy0 = 1.0f - wy1;
        int x0 = (int)x0f, y0 = (int)y0f;

        int b = (q >= boundary) ? 1 : 0;
        int lbase = (l >= 1 ? 16384 : 0) + (l >= 2 ? 4096 : 0) + (l >= 3 ? 1024 : 0);
        int base = b * ROWS_PER_B + lbase;

        int   xs[2]  = {x0, x0 + 1};
        int   ys2[2] = {y0, y0 + 1};
        float wxs[2] = {wx0, wx1};
        float wys[2] = {wy0, wy1};

#pragma unroll
        for (int cy = 0; cy < 2; cy++) {
#pragma unroll
            for (int cx = 0; cx < 2; cx++) {
                int c  = cy * 2 + cx;
                int xi = xs[cx], yi = ys2[cy];
                bool valid = (xi >= 0) & (xi < Wl) & (yi >= 0) & (yi < Wl);
                int xc = min(max(xi, 0), Wl - 1);
                int yc = min(max(yi, 0), Wl - 1);
                srow[qi][i][c] = base + yc * Wl + xc;
                swt [qi][i][c] = valid ? (aw * wys[cy] * wxs[cx]) : 0.0f;
            }
        }
    }
    __syncthreads();

    // gather: 32 threads per query, 8 channels each (16B loads)
    const int qi   = tid >> 5;
    const int tq   = tid & 31;
    const int h    = tq >> 2;
    const int coff = h * DH_ + (tq & 3) * 8;
    const int q    = q0 + qi;

    float acc[8];
#pragma unroll
    for (int e = 0; e < 8; e++) acc[e] = 0.0f;

#pragma unroll
    for (int lp = 0; lp < 16; lp++) {
        const int i = lp * 8 + h;
        int4   r4 = *(const int4*)  &srow[qi][i][0];
        float4 w4 = *(const float4*)&swt [qi][i][0];
        int   rr[4] = {r4.x, r4.y, r4.z, r4.w};
        float ww[4] = {w4.x, w4.y, w4.z, w4.w};
#pragma unroll
        for (int c = 0; c < 4; c++) {
            const uint4 v = __ldg((const uint4*)&g_vproj[(size_t)rr[c] * C_ + coff]);
            const __half2* hp = (const __half2*)&v;
            float w = ww[c];
#pragma unroll
            for (int e = 0; e < 4; e++) {
                float2 f = __half22float2(hp[e]);
                acc[e * 2 + 0] += w * f.x;
                acc[e * 2 + 1] += w * f.y;
            }
        }
    }
    uint4 outv;
    outv.x = pack_f16x2(acc[0], acc[1]);
    outv.y = pack_f16x2(acc[2], acc[3]);
    outv.z = pack_f16x2(acc[4], acc[5]);
    outv.w = pack_f16x2(acc[6], acc[7]);
    *(uint4*)&g_agg[(size_t)q * C_ + coff] = outv;
}

// ---------------------------------------------------------------------------
// kernel_launch
// ---------------------------------------------------------------------------
extern "C" void kernel_launch(void* const* d_in, const int* in_sizes, int n_in,
                              void* d_out, int out_size)
{
    const float* query  = (const float*)d_in[0];
    const float* ref    = (const float*)d_in[1];
    const float* values = (const float*)d_in[2];
    const float* W_so   = (const float*)d_in[3];
    const float* b_so   = (const float*)d_in[4];
    const float* W_aw   = (const float*)d_in[5];
    const float* b_aw   = (const float*)d_in[6];
    const float* W_v    = (const float*)d_in[7];
    const float* b_v    = (const float*)d_in[8];
    const float* W_o    = (const float*)d_in[9];
    const float* b_o    = (const float*)d_in[10];
    const int* batch_offsets = (const int*)d_in[11];
    float* out = (float*)d_out;
    (void)in_sizes; (void)n_in; (void)out_size;

    __half *vproj, *agg;
    float *offs, *awr;
    char *wvh, *wqc, *woh;
    cudaGetSymbolAddress((void**)&vproj, g_vproj);
    cudaGetSymbolAddress((void**)&offs,  g_offs);
    cudaGetSymbolAddress((void**)&awr,   g_awr);
    cudaGetSymbolAddress((void**)&agg,   g_agg);
    cudaGetSymbolAddress((void**)&wvh,   g_wvh_img);
    cudaGetSymbolAddress((void**)&wqc,   g_wqc_img);
    cudaGetSymbolAddress((void**)&woh,   g_woh_img);

    const int SMOUT = 61440;   // B resident 40960 + A ring 20480
    cudaFuncSetAttribute(gemm_out, cudaFuncAttributeMaxDynamicSharedMemorySize, SMOUT);

    // 0) weight images (single launch)
    prep_all<<<448, 256>>>(W_v, W_so, W_aw, W_o, wvh, wqc, woh);

    // 1) vproj + offs + awr, one fused launch (1448 CTAs, 8 warps each)
    gemm_all<<<NV_BLK + NQ_BLK, 256>>>(values, wvh, b_v, vproj,
                                       query, wqc, b_so, b_aw, offs, awr);

    // 2) softmax + bilinear sampling + head aggregation (fp16 agg out)
    sample_kernel<<<Q_ / QPB, 256>>>(ref, batch_offsets);

    // 3) out = agg @ W_o^T + b_o  [8192 x 256] (fp16 MMA, B-resident)
    {
        dim3 grid(Q_ / 64, 4);
        gemm_out<<<grid, 256, SMOUT>>>(agg, woh, b_o, out);
    }
}